// round 3
// baseline (speedup 1.0000x reference)
#include <cuda_runtime.h>
#include <cuda_bf16.h>

// Problem constants
#define NN 50000          // nodes
#define NE 800000         // edges (without self loops)
#define ET 850000         // edges + self loops
#define NG 64             // graphs
#define FD 128            // feature dim (F_IN == HID == 128)
#define NCLS 10
#define NEG_SLOPE 0.2f
#define SCAN_B 512
#define SCAN_NB ((NN + SCAN_B - 1) / SCAN_B)   // 98
#define NEG_BIG -3.0e38f

// ------------------- device scratch (static, no allocation) -------------------
__device__ float g_xl[NN * FD];
__device__ float g_xr[NN * FD];
__device__ float g_h0[NN * FD];
__device__ float g_h1[NN * FD];
__device__ int   g_deg[NN];
__device__ int   g_excl[NN];
__device__ int   g_blk[SCAN_NB];
__device__ int   g_rowptr[NN + 1];
__device__ int   g_fill[NN];
__device__ int   g_src[ET];
__device__ float g_pool[NG * FD];
__device__ float g_cnt[NG];
__device__ int   g_is64;          // 1 -> indices are int64, 0 -> int32

__device__ __forceinline__ float eluf(float x) {
    return x > 0.0f ? x : (__expf(x) - 1.0f);
}

// safe dual-dtype index load
__device__ __forceinline__ int load_idx(const void* p, long long i, int is64) {
    if (is64) return (int)(((const long long*)p)[i]);
    return ((const int*)p)[i];
}

// ------------------- dtype detection -------------------
// Reads first 64 values interpreted as int64 (first 512 bytes — safe for either dtype,
// buffer is >= 6.4 MB). If the data is really int32, an int64 read packs two int32s:
// value = lo + hi*2^32 with hi in [0, 50000), out of [0, NN) range almost surely.
__global__ void k_detect(const long long* __restrict__ ei) {
    if (threadIdx.x == 0 && blockIdx.x == 0) {
        int ok64 = 1;
        for (int i = 0; i < 64; i++) {
            long long v = ei[i];
            if (v < 0 || v >= (long long)NN) { ok64 = 0; break; }
        }
        g_is64 = ok64;
    }
}

// ------------------- CSR build -------------------
__global__ void k_init() {
    int i = blockIdx.x * blockDim.x + threadIdx.x;
    if (i < NN) { g_deg[i] = 1; g_fill[i] = 0; }   // deg starts at 1 for the self loop
    if (i < NG * FD) g_pool[i] = 0.0f;
    if (i < NG) g_cnt[i] = 0.0f;
}

__global__ void k_hist(const void* __restrict__ ei) {
    int e = blockIdx.x * blockDim.x + threadIdx.x;
    if (e < NE) {
        int d = load_idx(ei, (long long)NE + e, g_is64);
        atomicAdd(&g_deg[d], 1);
    }
}

__global__ void k_scan1() {
    __shared__ int sm[SCAN_B];
    int i = blockIdx.x * SCAN_B + threadIdx.x;
    int v = (i < NN) ? g_deg[i] : 0;
    sm[threadIdx.x] = v;
    __syncthreads();
    for (int o = 1; o < SCAN_B; o <<= 1) {
        int t = (threadIdx.x >= o) ? sm[threadIdx.x - o] : 0;
        __syncthreads();
        sm[threadIdx.x] += t;
        __syncthreads();
    }
    if (i < NN) g_excl[i] = sm[threadIdx.x] - v;
    if (threadIdx.x == SCAN_B - 1) g_blk[blockIdx.x] = sm[SCAN_B - 1];
}

__global__ void k_scan2() {
    if (threadIdx.x == 0) {
        int run = 0;
        for (int b = 0; b < SCAN_NB; b++) { int t = g_blk[b]; g_blk[b] = run; run += t; }
        g_rowptr[NN] = ET;
    }
}

__global__ void k_scan3() {
    int i = blockIdx.x * SCAN_B + threadIdx.x;
    if (i < NN) g_rowptr[i] = g_excl[i] + g_blk[blockIdx.x];
}

__global__ void k_scatter(const void* __restrict__ ei) {
    int e = blockIdx.x * blockDim.x + threadIdx.x;
    if (e >= ET) return;
    int s, d;
    if (e < NE) {
        int is64 = g_is64;
        s = load_idx(ei, e, is64);
        d = load_idx(ei, (long long)NE + e, is64);
    } else {
        s = e - NE; d = e - NE;
    }
    int pos = g_rowptr[d] + atomicAdd(&g_fill[d], 1);
    g_src[pos] = s;
}

// ------------------- GEMM: out = A @ W + b  (N x 128 @ 128 x 128) -------------------
// ASEL: 0 -> param x, 1 -> g_h0, 2 -> g_h1.  SIDE: 0 -> g_xl, 1 -> g_xr.
#define BM 64
#define BK 32
template<int ASEL, int SIDE>
__global__ void k_gemm(const float* __restrict__ Aparam,
                       const float* __restrict__ W,
                       const float* __restrict__ bias)
{
    const float* A = (ASEL == 0) ? Aparam : (ASEL == 1 ? g_h0 : g_h1);
    float* out     = (SIDE == 0) ? g_xl : g_xr;

    __shared__ float As[BM][BK + 1];
    __shared__ float Bs[BK][FD];

    int tid = threadIdx.x;          // 256 threads
    int tx  = tid & 15;             // column group
    int ty  = tid >> 4;             // row group
    int rowBase = blockIdx.x * BM;

    float acc[4][8];
#pragma unroll
    for (int r = 0; r < 4; r++)
#pragma unroll
        for (int c = 0; c < 8; c++) acc[r][c] = 0.0f;

    for (int kb = 0; kb < FD; kb += BK) {
#pragma unroll
        for (int j = 0; j < 8; j++) {               // A tile: 64x32
            int idx = j * 256 + tid;
            int r = idx >> 5, c = idx & 31;
            int gr = rowBase + r;
            As[r][c] = (gr < NN) ? A[gr * FD + kb + c] : 0.0f;
        }
#pragma unroll
        for (int j = 0; j < 16; j++) {              // B tile: 32x128
            int idx = j * 256 + tid;
            int r = idx >> 7, c = idx & 127;
            Bs[r][c] = W[(kb + r) * FD + c];
        }
        __syncthreads();
#pragma unroll
        for (int kk = 0; kk < BK; kk++) {
            float a[4], b[8];
#pragma unroll
            for (int r = 0; r < 4; r++) a[r] = As[ty * 4 + r][kk];
#pragma unroll
            for (int c = 0; c < 8; c++) b[c] = Bs[kk][tx + 16 * c];
#pragma unroll
            for (int r = 0; r < 4; r++)
#pragma unroll
                for (int c = 0; c < 8; c++)
                    acc[r][c] = fmaf(a[r], b[c], acc[r][c]);
        }
        __syncthreads();
    }
#pragma unroll
    for (int r = 0; r < 4; r++) {
        int gr = rowBase + ty * 4 + r;
        if (gr < NN) {
#pragma unroll
            for (int c = 0; c < 8; c++) {
                int col = tx + 16 * c;
                out[gr * FD + col] = acc[r][c] + bias[col];
            }
        }
    }
}

// ------------------- fused edge scoring + online softmax + aggregation -------------------
// one 128-thread block per destination node; warp w == head w; thread = (head, channel)
// OSEL: 0 -> g_h0, 1 -> g_h1
template<int OSEL>
__global__ void k_aggr(const float* __restrict__ att, const float* __restrict__ bias)
{
    float* hout = (OSEL == 0) ? g_h0 : g_h1;
    int i   = blockIdx.x;
    int tid = threadIdx.x;

    float rx = g_xr[i * FD + tid];
    float at = att[tid];
    int beg = g_rowptr[i], end = g_rowptr[i + 1];

    float m = NEG_BIG, den = 0.0f, acc = 0.0f;

    for (int e = beg; e < end; e++) {
        int s = g_src[e];
        float v = g_xl[s * FD + tid];
        float t  = v + rx;
        float lr = t > 0.0f ? t : NEG_SLOPE * t;
        float p  = lr * at;
#pragma unroll
        for (int o = 16; o; o >>= 1) p += __shfl_xor_sync(0xffffffffu, p, o);
        // online softmax update (per warp / per head)
        float nm = fmaxf(m, p);
        float f  = __expf(m - nm);
        float w  = __expf(p - nm);
        den = den * f + w;
        acc = acc * f + w * v;
        m = nm;
    }
    hout[i * FD + tid] = eluf(acc / den + bias[tid]);
}

// ------------------- global mean pool -------------------
__global__ void k_pool(const void* __restrict__ batch)
{
    int idx = blockIdx.x * blockDim.x + threadIdx.x;
    if (idx >= NN * FD) return;
    int n = idx >> 7, f = idx & 127;
    int g = load_idx(batch, n, g_is64);
    atomicAdd(&g_pool[g * FD + f], g_h0[idx]);   // final layer output lives in g_h0
    if (f == 0) atomicAdd(&g_cnt[g], 1.0f);
}

// ------------------- final linear + elu + log_softmax: one block per graph -------------------
__global__ void k_final(const float* __restrict__ lw, const float* __restrict__ lb,
                        float* __restrict__ out)
{
    __shared__ float sh[NCLS];
    int g = blockIdx.x;
    int j = threadIdx.x;           // 32 threads, first 10 active
    if (j < NCLS) {
        float cnt = fmaxf(g_cnt[g], 1.0f);
        float s = lb[j];
        for (int f = 0; f < FD; f++)
            s += (g_pool[g * FD + f] / cnt) * lw[f * NCLS + j];
        sh[j] = eluf(s);
    }
    __syncthreads();
    if (j < NCLS) {
        float mx = NEG_BIG;
#pragma unroll
        for (int jj = 0; jj < NCLS; jj++) mx = fmaxf(mx, sh[jj]);
        float ls = 0.0f;
#pragma unroll
        for (int jj = 0; jj < NCLS; jj++) ls += __expf(sh[jj] - mx);
        out[g * NCLS + j] = sh[j] - mx - __logf(ls);
    }
}

// ------------------- launch -------------------
extern "C" void kernel_launch(void* const* d_in, const int* in_sizes, int n_in,
                              void* d_out, int out_size)
{
    const float* x    = (const float*)d_in[0];
    const void*  ei   = d_in[1];                     // int32 or int64, detected on device
    const void*  bat  = d_in[2];
    const float* Wl   = (const float*)d_in[3];       // [3,128,128]
    const float* Wr   = (const float*)d_in[4];
    const float* bl   = (const float*)d_in[5];       // [3,128]
    const float* br   = (const float*)d_in[6];
    const float* att  = (const float*)d_in[7];       // [3,4,32]
    const float* bias = (const float*)d_in[8];       // [3,128]
    const float* lw   = (const float*)d_in[9];       // [128,10]
    const float* lb   = (const float*)d_in[10];      // [10]
    float* out = (float*)d_out;

    // dtype detect + CSR build (reused by all 3 layers)
    k_detect<<<1, 32>>>((const long long*)ei);
    k_init<<<(NN + 255) / 256, 256>>>();
    k_hist<<<(NE + 255) / 256, 256>>>(ei);
    k_scan1<<<SCAN_NB, SCAN_B>>>();
    k_scan2<<<1, 32>>>();
    k_scan3<<<SCAN_NB, SCAN_B>>>();
    k_scatter<<<(ET + 255) / 256, 256>>>(ei);

    int gblocks = (NN + BM - 1) / BM;
    // layer 0: A = x -> g_h0
    k_gemm<0, 0><<<gblocks, 256>>>(x, Wl + 0 * FD * FD, bl + 0 * FD);
    k_gemm<0, 1><<<gblocks, 256>>>(x, Wr + 0 * FD * FD, br + 0 * FD);
    k_aggr<0><<<NN, FD>>>(att + 0 * FD, bias + 0 * FD);
    // layer 1: A = g_h0 -> g_h1
    k_gemm<1, 0><<<gblocks, 256>>>(x, Wl + 1 * FD * FD, bl + 1 * FD);
    k_gemm<1, 1><<<gblocks, 256>>>(x, Wr + 1 * FD * FD, br + 1 * FD);
    k_aggr<1><<<NN, FD>>>(att + 1 * FD, bias + 1 * FD);
    // layer 2: A = g_h1 -> g_h0
    k_gemm<2, 0><<<gblocks, 256>>>(x, Wl + 2 * FD * FD, bl + 2 * FD);
    k_gemm<2, 1><<<gblocks, 256>>>(x, Wr + 2 * FD * FD, br + 2 * FD);
    k_aggr<0><<<NN, FD>>>(att + 2 * FD, bias + 2 * FD);

    // pool + head
    k_pool<<<(NN * FD + 255) / 256, 256>>>(bat);
    k_final<<<NG, 32>>>(lw, lb, out);
}

// round 4
// speedup vs baseline: 1.0222x; 1.0222x over previous
#include <cuda_runtime.h>
#include <cuda_bf16.h>

// Problem constants
#define NN 50000          // nodes
#define NE 800000         // edges (without self loops)
#define ET 850000         // edges + self loops
#define NG 64             // graphs
#define FD 128            // feature dim (F_IN == HID == 128)
#define NCLS 10
#define NEG_SLOPE 0.2f
#define SCAN_B 512
#define SCAN_NB ((NN + SCAN_B - 1) / SCAN_B)   // 98
#define NEG_BIG -3.0e38f

// ------------------- device scratch (static, no allocation) -------------------
__device__ float g_xl[NN * FD];
__device__ float g_xr[NN * FD];
__device__ float g_h0[NN * FD];
__device__ float g_h1[NN * FD];
__device__ int   g_deg[NN];
__device__ int   g_excl[NN];
__device__ int   g_blk[SCAN_NB];
__device__ int   g_rowptr[NN + 1];
__device__ int   g_fill[NN];
__device__ int   g_src[ET];
__device__ float g_pool[NG * FD];
__device__ float g_cnt[NG];
__device__ int   g_is64;          // 1 -> indices are int64, 0 -> int32

__device__ __forceinline__ float eluf(float x) {
    return x > 0.0f ? x : (__expf(x) - 1.0f);
}

__device__ __forceinline__ int load_idx(const void* p, long long i, int is64) {
    if (is64) return (int)(((const long long*)p)[i]);
    return ((const int*)p)[i];
}

// ------------------- dtype detection -------------------
__global__ void k_detect(const long long* __restrict__ ei) {
    if (threadIdx.x == 0 && blockIdx.x == 0) {
        int ok64 = 1;
        for (int i = 0; i < 64; i++) {
            long long v = ei[i];
            if (v < 0 || v >= (long long)NN) { ok64 = 0; break; }
        }
        g_is64 = ok64;
    }
}

// ------------------- CSR build -------------------
__global__ void k_init() {
    int i = blockIdx.x * blockDim.x + threadIdx.x;
    if (i < NN) { g_deg[i] = 1; g_fill[i] = 0; }   // self loop
    if (i < NG * FD) g_pool[i] = 0.0f;
    if (i < NG) g_cnt[i] = 0.0f;
}

__global__ void k_hist(const void* __restrict__ ei) {
    int e = blockIdx.x * blockDim.x + threadIdx.x;
    if (e < NE) {
        int d = load_idx(ei, (long long)NE + e, g_is64);
        atomicAdd(&g_deg[d], 1);
    }
}

__global__ void k_scan1() {
    __shared__ int sm[SCAN_B];
    int i = blockIdx.x * SCAN_B + threadIdx.x;
    int v = (i < NN) ? g_deg[i] : 0;
    sm[threadIdx.x] = v;
    __syncthreads();
    for (int o = 1; o < SCAN_B; o <<= 1) {
        int t = (threadIdx.x >= o) ? sm[threadIdx.x - o] : 0;
        __syncthreads();
        sm[threadIdx.x] += t;
        __syncthreads();
    }
    if (i < NN) g_excl[i] = sm[threadIdx.x] - v;
    if (threadIdx.x == SCAN_B - 1) g_blk[blockIdx.x] = sm[SCAN_B - 1];
}

__global__ void k_scan2() {
    if (threadIdx.x == 0) {
        int run = 0;
        for (int b = 0; b < SCAN_NB; b++) { int t = g_blk[b]; g_blk[b] = run; run += t; }
        g_rowptr[NN] = ET;
    }
}

__global__ void k_scan3() {
    int i = blockIdx.x * SCAN_B + threadIdx.x;
    if (i < NN) g_rowptr[i] = g_excl[i] + g_blk[blockIdx.x];
}

__global__ void k_scatter(const void* __restrict__ ei) {
    int e = blockIdx.x * blockDim.x + threadIdx.x;
    if (e >= ET) return;
    int s, d;
    if (e < NE) {
        int is64 = g_is64;
        s = load_idx(ei, e, is64);
        d = load_idx(ei, (long long)NE + e, is64);
    } else {
        s = e - NE; d = e - NE;
    }
    int pos = g_rowptr[d] + atomicAdd(&g_fill[d], 1);
    g_src[pos] = s;
}

// ------------------- GEMM: out = A @ W + b  (50000x128 @ 128x128) -------------------
// 128x128 block tile, BK=16, 256 threads, 8x8 microtile, float4 everywhere.
// ASEL: 0 -> param x, 1 -> g_h0, 2 -> g_h1.  SIDE: 0 -> g_xl, 1 -> g_xr.
#define GBM 128
#define GBK 16
#define ASPAD 132   // As row stride (floats): 132*4B=528B, 16B-aligned, depitches banks
template<int ASEL, int SIDE>
__global__ void __launch_bounds__(256, 2) k_gemm(const float* __restrict__ Aparam,
                                                 const float* __restrict__ W,
                                                 const float* __restrict__ bias)
{
    const float* A = (ASEL == 0) ? Aparam : (ASEL == 1 ? g_h0 : g_h1);
    float* out     = (SIDE == 0) ? g_xl : g_xr;

    __shared__ float As[GBK * ASPAD];     // k-major: As[k*ASPAD + m]
    __shared__ float Bs[GBK * FD];        // Bs[k*FD + n]

    const int tid = threadIdx.x;          // 256
    const int tx  = tid & 15;             // n group
    const int ty  = tid >> 4;             // m group
    const int m0  = ty * 8;
    const int n0  = tx * 8;
    const int rowBase = blockIdx.x * GBM;

    float acc[8][8];
#pragma unroll
    for (int r = 0; r < 8; r++)
#pragma unroll
        for (int c = 0; c < 8; c++) acc[r][c] = 0.0f;

    // global-load coordinates (tile = 512 float4; 2 per thread)
    // A: float4 f -> row = f>>2, c4 = f&3
    const int a_r0 = tid >> 2, a_c0 = (tid & 3) * 4;         // f = tid
    const int a_r1 = (tid + 256) >> 2, a_c1 = a_c0;          // f = tid+256 (same c4 pattern)
    // B: float4 f -> row = f>>5, col4 = f&31
    const int b_r0 = tid >> 5, b_c0 = (tid & 31) * 4;
    const int b_r1 = (tid + 256) >> 5, b_c1 = b_c0;

    for (int kb = 0; kb < FD; kb += GBK) {
        // ---- load A tile (transposed into k-major smem) ----
        float4 av0 = make_float4(0.f, 0.f, 0.f, 0.f), av1 = av0;
        if (rowBase + a_r0 < NN)
            av0 = *(const float4*)&A[(rowBase + a_r0) * FD + kb + a_c0];
        if (rowBase + a_r1 < NN)
            av1 = *(const float4*)&A[(rowBase + a_r1) * FD + kb + a_c1];
        As[(a_c0 + 0) * ASPAD + a_r0] = av0.x;
        As[(a_c0 + 1) * ASPAD + a_r0] = av0.y;
        As[(a_c0 + 2) * ASPAD + a_r0] = av0.z;
        As[(a_c0 + 3) * ASPAD + a_r0] = av0.w;
        As[(a_c1 + 0) * ASPAD + a_r1] = av1.x;
        As[(a_c1 + 1) * ASPAD + a_r1] = av1.y;
        As[(a_c1 + 2) * ASPAD + a_r1] = av1.z;
        As[(a_c1 + 3) * ASPAD + a_r1] = av1.w;
        // ---- load B tile ----
        *(float4*)&Bs[b_r0 * FD + b_c0] = *(const float4*)&W[(kb + b_r0) * FD + b_c0];
        *(float4*)&Bs[b_r1 * FD + b_c1] = *(const float4*)&W[(kb + b_r1) * FD + b_c1];
        __syncthreads();

#pragma unroll
        for (int kk = 0; kk < GBK; kk++) {
            float4 a03 = *(const float4*)&As[kk * ASPAD + m0];
            float4 a47 = *(const float4*)&As[kk * ASPAD + m0 + 4];
            float4 b03 = *(const float4*)&Bs[kk * FD + n0];
            float4 b47 = *(const float4*)&Bs[kk * FD + n0 + 4];
            float a[8] = {a03.x, a03.y, a03.z, a03.w, a47.x, a47.y, a47.z, a47.w};
            float b[8] = {b03.x, b03.y, b03.z, b03.w, b47.x, b47.y, b47.z, b47.w};
#pragma unroll
            for (int r = 0; r < 8; r++)
#pragma unroll
                for (int c = 0; c < 8; c++)
                    acc[r][c] = fmaf(a[r], b[c], acc[r][c]);
        }
        __syncthreads();
    }

    float4 bia0 = *(const float4*)&bias[n0];
    float4 bia1 = *(const float4*)&bias[n0 + 4];
#pragma unroll
    for (int r = 0; r < 8; r++) {
        int gr = rowBase + m0 + r;
        if (gr < NN) {
            float4 o0 = make_float4(acc[r][0] + bia0.x, acc[r][1] + bia0.y,
                                    acc[r][2] + bia0.z, acc[r][3] + bia0.w);
            float4 o1 = make_float4(acc[r][4] + bia1.x, acc[r][5] + bia1.y,
                                    acc[r][6] + bia1.z, acc[r][7] + bia1.w);
            *(float4*)&out[gr * FD + n0]     = o0;
            *(float4*)&out[gr * FD + n0 + 4] = o1;
        }
    }
}

// ------------------- fused edge scoring + online softmax + aggregation -------------------
// one 128-thread block per destination node; warp w == head w; thread = (head, channel)
// OSEL: 0 -> g_h0, 1 -> g_h1.  POOL: also accumulate mean-pool (final layer).
template<int OSEL, int POOL>
__global__ void __launch_bounds__(128) k_aggr(const float* __restrict__ att,
                                              const float* __restrict__ bias,
                                              const void* __restrict__ batch)
{
    float* hout = (OSEL == 0) ? g_h0 : g_h1;
    int i   = blockIdx.x;
    int tid = threadIdx.x;

    float rx = g_xr[i * FD + tid];
    float at = att[tid];
    int beg = g_rowptr[i], end = g_rowptr[i + 1];

    float m = NEG_BIG, den = 0.0f, acc = 0.0f;

    // software-pipelined gather (deg >= 1 always: self loop)
    int s = g_src[beg];
    float v = g_xl[s * FD + tid];
    for (int e = beg; e < end; e++) {
        float vc = v;
        int en = e + 1;
        if (en < end) {
            int sn = g_src[en];
            v = g_xl[sn * FD + tid];
        }
        float t  = vc + rx;
        float lr = t > 0.0f ? t : NEG_SLOPE * t;
        float p  = lr * at;
#pragma unroll
        for (int o = 16; o; o >>= 1) p += __shfl_xor_sync(0xffffffffu, p, o);
        float nm = fmaxf(m, p);
        float f  = __expf(m - nm);
        float w  = __expf(p - nm);
        den = den * f + w;
        acc = acc * f + w * vc;
        m = nm;
    }
    float val = eluf(acc / den + bias[tid]);
    hout[i * FD + tid] = val;
    if (POOL) {
        int g = load_idx(batch, i, g_is64);
        atomicAdd(&g_pool[g * FD + tid], val);
        if (tid == 0) atomicAdd(&g_cnt[g], 1.0f);
    }
}

// ------------------- final linear + elu + log_softmax: one block per graph -------------------
__global__ void k_final(const float* __restrict__ lw, const float* __restrict__ lb,
                        float* __restrict__ out)
{
    __shared__ float sh[NCLS];
    int g = blockIdx.x;
    int j = threadIdx.x;           // 32 threads, first 10 active
    if (j < NCLS) {
        float cnt = fmaxf(g_cnt[g], 1.0f);
        float s = lb[j];
        for (int f = 0; f < FD; f++)
            s += (g_pool[g * FD + f] / cnt) * lw[f * NCLS + j];
        sh[j] = eluf(s);
    }
    __syncthreads();
    if (j < NCLS) {
        float mx = NEG_BIG;
#pragma unroll
        for (int jj = 0; jj < NCLS; jj++) mx = fmaxf(mx, sh[jj]);
        float ls = 0.0f;
#pragma unroll
        for (int jj = 0; jj < NCLS; jj++) ls += __expf(sh[jj] - mx);
        out[g * NCLS + j] = sh[j] - mx - __logf(ls);
    }
}

// ------------------- launch -------------------
extern "C" void kernel_launch(void* const* d_in, const int* in_sizes, int n_in,
                              void* d_out, int out_size)
{
    const float* x    = (const float*)d_in[0];
    const void*  ei   = d_in[1];                     // int32 or int64, detected on device
    const void*  bat  = d_in[2];
    const float* Wl   = (const float*)d_in[3];       // [3,128,128]
    const float* Wr   = (const float*)d_in[4];
    const float* bl   = (const float*)d_in[5];       // [3,128]
    const float* br   = (const float*)d_in[6];
    const float* att  = (const float*)d_in[7];       // [3,4,32]
    const float* bias = (const float*)d_in[8];       // [3,128]
    const float* lw   = (const float*)d_in[9];       // [128,10]
    const float* lb   = (const float*)d_in[10];      // [10]
    float* out = (float*)d_out;

    // dtype detect + CSR build (reused by all 3 layers)
    k_detect<<<1, 32>>>((const long long*)ei);
    k_init<<<(NN + 255) / 256, 256>>>();
    k_hist<<<(NE + 255) / 256, 256>>>(ei);
    k_scan1<<<SCAN_NB, SCAN_B>>>();
    k_scan2<<<1, 32>>>();
    k_scan3<<<SCAN_NB, SCAN_B>>>();
    k_scatter<<<(ET + 255) / 256, 256>>>(ei);

    int gblocks = (NN + GBM - 1) / GBM;   // 391
    // layer 0: A = x -> g_h0
    k_gemm<0, 0><<<gblocks, 256>>>(x, Wl + 0 * FD * FD, bl + 0 * FD);
    k_gemm<0, 1><<<gblocks, 256>>>(x, Wr + 0 * FD * FD, br + 0 * FD);
    k_aggr<0, 0><<<NN, FD>>>(att + 0 * FD, bias + 0 * FD, bat);
    // layer 1: A = g_h0 -> g_h1
    k_gemm<1, 0><<<gblocks, 256>>>(x, Wl + 1 * FD * FD, bl + 1 * FD);
    k_gemm<1, 1><<<gblocks, 256>>>(x, Wr + 1 * FD * FD, br + 1 * FD);
    k_aggr<1, 0><<<NN, FD>>>(att + 1 * FD, bias + 1 * FD, bat);
    // layer 2: A = g_h1 -> g_h0, fused mean-pool accumulate
    k_gemm<2, 0><<<gblocks, 256>>>(x, Wl + 2 * FD * FD, bl + 2 * FD);
    k_gemm<2, 1><<<gblocks, 256>>>(x, Wr + 2 * FD * FD, br + 2 * FD);
    k_aggr<0, 1><<<NN, FD>>>(att + 2 * FD, bias + 2 * FD, bat);

    // head
    k_final<<<NG, 32>>>(lw, lb, out);
}

// round 8
// speedup vs baseline: 1.2511x; 1.2240x over previous
#include <cuda_runtime.h>
#include <cuda_bf16.h>
#include <cstdint>

// Problem constants
#define NN 50000
#define NE 800000
#define ET 850000
#define NG 64
#define FD 128
#define NCLS 10
#define NEG_SLOPE 0.2f
#define SCAN_B 512
#define SCAN_NB ((NN + SCAN_B - 1) / SCAN_B)
#define NEG_BIG -3.0e38f

// ------------------- device scratch -------------------
__device__ float g_xl[NN * FD];
__device__ float g_xr[NN * FD];
__device__ float g_h0[NN * FD];
__device__ float g_h1[NN * FD];
__device__ __nv_bfloat16 g_wthi[6 * FD * FD];   // [layer*2+side][n][k]
__device__ __nv_bfloat16 g_wtlo[6 * FD * FD];
__device__ int   g_deg[NN];
__device__ int   g_excl[NN];
__device__ int   g_blk[SCAN_NB];
__device__ int   g_rowptr[NN + 1];
__device__ int   g_fill[NN];
__device__ int   g_src[ET];
__device__ float g_pool[NG * FD];
__device__ float g_cnt[NG];
__device__ int   g_is64;

__device__ __forceinline__ float eluf(float x) {
    return x > 0.0f ? x : (__expf(x) - 1.0f);
}

__device__ __forceinline__ int load_idx(const void* p, long long i, int is64) {
    if (is64) return (int)(((const long long*)p)[i]);
    return ((const int*)p)[i];
}

__device__ __forceinline__ uint32_t pack_bf2(float a, float b) {
    __nv_bfloat162 h = __floats2bfloat162_rn(a, b);
    return *(uint32_t*)&h;
}

// ------------------- dtype detection -------------------
__global__ void k_detect(const long long* __restrict__ ei) {
    if (threadIdx.x == 0 && blockIdx.x == 0) {
        int ok64 = 1;
        for (int i = 0; i < 64; i++) {
            long long v = ei[i];
            if (v < 0 || v >= (long long)NN) { ok64 = 0; break; }
        }
        g_is64 = ok64;
    }
}

// ------------------- CSR build -------------------
__global__ void k_init() {
    int i = blockIdx.x * blockDim.x + threadIdx.x;
    if (i < NN) { g_deg[i] = 1; g_fill[i] = 0; }
    if (i < NG * FD) g_pool[i] = 0.0f;
    if (i < NG) g_cnt[i] = 0.0f;
}

__global__ void k_hist(const void* __restrict__ ei) {
    int e = blockIdx.x * blockDim.x + threadIdx.x;
    if (e < NE) atomicAdd(&g_deg[load_idx(ei, (long long)NE + e, g_is64)], 1);
}

__global__ void k_scan1() {
    __shared__ int sm[SCAN_B];
    int i = blockIdx.x * SCAN_B + threadIdx.x;
    int v = (i < NN) ? g_deg[i] : 0;
    sm[threadIdx.x] = v;
    __syncthreads();
    for (int o = 1; o < SCAN_B; o <<= 1) {
        int t = (threadIdx.x >= o) ? sm[threadIdx.x - o] : 0;
        __syncthreads();
        sm[threadIdx.x] += t;
        __syncthreads();
    }
    if (i < NN) g_excl[i] = sm[threadIdx.x] - v;
    if (threadIdx.x == SCAN_B - 1) g_blk[blockIdx.x] = sm[SCAN_B - 1];
}

__global__ void k_scan2() {
    if (threadIdx.x == 0) {
        int run = 0;
        for (int b = 0; b < SCAN_NB; b++) { int t = g_blk[b]; g_blk[b] = run; run += t; }
        g_rowptr[NN] = ET;
    }
}

__global__ void k_scan3() {
    int i = blockIdx.x * SCAN_B + threadIdx.x;
    if (i < NN) g_rowptr[i] = g_excl[i] + g_blk[blockIdx.x];
}

__global__ void k_scatter(const void* __restrict__ ei) {
    int e = blockIdx.x * blockDim.x + threadIdx.x;
    if (e >= ET) return;
    int s, d;
    if (e < NE) {
        int is64 = g_is64;
        s = load_idx(ei, e, is64);
        d = load_idx(ei, (long long)NE + e, is64);
    } else {
        s = e - NE; d = e - NE;
    }
    int pos = g_rowptr[d] + atomicAdd(&g_fill[d], 1);
    g_src[pos] = s;
}

// ------------------- W transpose + hi/lo split (one-time) -------------------
__global__ void k_convW(const float* __restrict__ Wl, const float* __restrict__ Wr) {
    int i = blockIdx.x * blockDim.x + threadIdx.x;   // over 3*128*128
    if (i >= 3 * FD * FD) return;
    int l = i >> 14, r = i & 16383;
    int k = r >> 7, n = r & 127;
    float a = Wl[l * FD * FD + k * FD + n];
    __nv_bfloat16 ah = __float2bfloat16(a);
    g_wthi[(l * 2 + 0) * FD * FD + n * FD + k] = ah;
    g_wtlo[(l * 2 + 0) * FD * FD + n * FD + k] = __float2bfloat16(a - __bfloat162float(ah));
    float b = Wr[l * FD * FD + k * FD + n];
    __nv_bfloat16 bh = __float2bfloat16(b);
    g_wthi[(l * 2 + 1) * FD * FD + n * FD + k] = bh;
    g_wtlo[(l * 2 + 1) * FD * FD + n * FD + k] = __float2bfloat16(b - __bfloat162float(bh));
}

// ------------------- mma.sync bf16 split-2 GEMM: out = A @ W + b -------------------
// 128x128 block tile, 8 warps (warp = 32m x 64n), K chunked by 32.
// smem rows padded to stride 40 bf16 (80 B): fragment LDS is bank-conflict-free.
#define KSTR 40

#define MMA_BF16(c, a, b0v, b1v) \
    asm volatile("mma.sync.aligned.m16n8k16.row.col.f32.bf16.bf16.f32 " \
        "{%0,%1,%2,%3}, {%4,%5,%6,%7}, {%8,%9}, {%0,%1,%2,%3};" \
        : "+f"((c)[0]), "+f"((c)[1]), "+f"((c)[2]), "+f"((c)[3]) \
        : "r"((a)[0]), "r"((a)[1]), "r"((a)[2]), "r"((a)[3]), "r"(b0v), "r"(b1v))

template<int ASEL, int SIDE, int WIDX>
__global__ void __launch_bounds__(256, 2) k_gemm_w(const float* __restrict__ Aparam,
                                                   const float* __restrict__ bias)
{
    const float* A = (ASEL == 0) ? Aparam : (ASEL == 1 ? g_h0 : g_h1);
    float* out     = SIDE ? g_xr : g_xl;

    __shared__ __nv_bfloat16 sAhi[128 * KSTR];
    __shared__ __nv_bfloat16 sAlo[128 * KSTR];
    __shared__ __nv_bfloat16 sWhi[128 * KSTR];
    __shared__ __nv_bfloat16 sWlo[128 * KSTR];

    const int tid  = threadIdx.x;
    const int wid  = tid >> 5;
    const int lane = tid & 31;
    const int grp  = lane >> 2;        // 0..7
    const int tig  = lane & 3;         // 0..3
    const int mstrip = (wid & 3) * 32;
    const int nstrip = (wid >> 2) * 64;
    const int rowBase = blockIdx.x * 128;

    float acc[2][8][4];
#pragma unroll
    for (int mt = 0; mt < 2; mt++)
#pragma unroll
        for (int nt = 0; nt < 8; nt++)
#pragma unroll
            for (int q = 0; q < 4; q++) acc[mt][nt][q] = 0.0f;

    for (int kb = 0; kb < FD; kb += 32) {
        // ---- A: fp32 -> bf16 hi/lo into smem (4 float4 per thread) ----
#pragma unroll
        for (int i = 0; i < 4; i++) {
            int f = tid + i * 256;          // 0..1023
            int r = f >> 3;
            int c = (f & 7) * 4;
            int gr = rowBase + r;
            float4 v = make_float4(0.f, 0.f, 0.f, 0.f);
            if (gr < NN) v = *(const float4*)&A[(size_t)gr * FD + kb + c];
            __nv_bfloat16 hx = __float2bfloat16(v.x), hy = __float2bfloat16(v.y);
            __nv_bfloat16 hz = __float2bfloat16(v.z), hw = __float2bfloat16(v.w);
            uint32_t h0 = pack_bf2(__bfloat162float(hx), __bfloat162float(hy));
            uint32_t h1 = pack_bf2(__bfloat162float(hz), __bfloat162float(hw));
            uint32_t l0 = pack_bf2(v.x - __bfloat162float(hx), v.y - __bfloat162float(hy));
            uint32_t l1 = pack_bf2(v.z - __bfloat162float(hz), v.w - __bfloat162float(hw));
            int si = r * KSTR + c;
            *(uint32_t*)&sAhi[si]     = h0;
            *(uint32_t*)&sAhi[si + 2] = h1;
            *(uint32_t*)&sAlo[si]     = l0;
            *(uint32_t*)&sAlo[si + 2] = l1;
        }
        // ---- W tiles: bf16 [n][k] -> smem (2 uint4 each for hi and lo) ----
        const __nv_bfloat16* wh = &g_wthi[(size_t)WIDX * FD * FD];
        const __nv_bfloat16* wl = &g_wtlo[(size_t)WIDX * FD * FD];
#pragma unroll
        for (int i = 0; i < 2; i++) {
            int f = tid + i * 256;          // 0..511
            int n = f >> 2;
            int c8 = (f & 3) * 8;
            uint4 vh = *(const uint4*)&wh[(size_t)n * FD + kb + c8];
            uint4 vl = *(const uint4*)&wl[(size_t)n * FD + kb + c8];
            int si = n * KSTR + c8;
            *(uint4*)&sWhi[si] = vh;
            *(uint4*)&sWlo[si] = vl;
        }
        __syncthreads();

#pragma unroll
        for (int s = 0; s < 2; s++) {
            const int ks = s * 16;
            uint32_t ah[2][4], al[2][4];
#pragma unroll
            for (int mt = 0; mt < 2; mt++) {
                int r0 = mstrip + mt * 16 + grp;
                int i00 = r0 * KSTR + ks + 2 * tig;
                int i10 = (r0 + 8) * KSTR + ks + 2 * tig;
                ah[mt][0] = *(uint32_t*)&sAhi[i00];
                ah[mt][1] = *(uint32_t*)&sAhi[i10];
                ah[mt][2] = *(uint32_t*)&sAhi[i00 + 8];
                ah[mt][3] = *(uint32_t*)&sAhi[i10 + 8];
                al[mt][0] = *(uint32_t*)&sAlo[i00];
                al[mt][1] = *(uint32_t*)&sAlo[i10];
                al[mt][2] = *(uint32_t*)&sAlo[i00 + 8];
                al[mt][3] = *(uint32_t*)&sAlo[i10 + 8];
            }
#pragma unroll
            for (int nt = 0; nt < 8; nt++) {
                int n = nstrip + nt * 8 + grp;
                int ib = n * KSTR + ks + 2 * tig;
                uint32_t bh0 = *(uint32_t*)&sWhi[ib];
                uint32_t bh1 = *(uint32_t*)&sWhi[ib + 8];
                uint32_t bl0 = *(uint32_t*)&sWlo[ib];
                uint32_t bl1 = *(uint32_t*)&sWlo[ib + 8];
#pragma unroll
                for (int mt = 0; mt < 2; mt++) {
                    MMA_BF16(acc[mt][nt], ah[mt], bh0, bh1);
                    MMA_BF16(acc[mt][nt], al[mt], bh0, bh1);
                    MMA_BF16(acc[mt][nt], ah[mt], bl0, bl1);
                }
            }
        }
        __syncthreads();
    }

    // ---- epilogue ----
#pragma unroll
    for (int nt = 0; nt < 8; nt++) {
        int col = nstrip + nt * 8 + 2 * tig;
        float2 bv = *(const float2*)&bias[col];
#pragma unroll
        for (int mt = 0; mt < 2; mt++) {
            int r0 = rowBase + mstrip + mt * 16 + grp;
            if (r0 < NN) {
                float2 o0 = make_float2(acc[mt][nt][0] + bv.x, acc[mt][nt][1] + bv.y);
                *(float2*)&out[(size_t)r0 * FD + col] = o0;
            }
            if (r0 + 8 < NN) {
                float2 o1 = make_float2(acc[mt][nt][2] + bv.x, acc[mt][nt][3] + bv.y);
                *(float2*)&out[(size_t)(r0 + 8) * FD + col] = o1;
            }
        }
    }
}

// ------------------- fused edge scoring + online softmax + aggregation -------------------
template<int OSEL, int POOL>
__global__ void __launch_bounds__(128) k_aggr(const float* __restrict__ att,
                                              const float* __restrict__ bias,
                                              const void* __restrict__ batch)
{
    float* hout = (OSEL == 0) ? g_h0 : g_h1;
    int i   = blockIdx.x;
    int tid = threadIdx.x;

    float rx = g_xr[i * FD + tid];
    float at = att[tid];
    int beg = g_rowptr[i], end = g_rowptr[i + 1];

    float m = NEG_BIG, den = 0.0f, acc = 0.0f;

    int s = g_src[beg];
    float v = g_xl[s * FD + tid];
    for (int e = beg; e < end; e++) {
        float vc = v;
        int en = e + 1;
        if (en < end) {
            int sn = g_src[en];
            v = g_xl[sn * FD + tid];
        }
        float t  = vc + rx;
        float lr = t > 0.0f ? t : NEG_SLOPE * t;
        float p  = lr * at;
#pragma unroll
        for (int o = 16; o; o >>= 1) p += __shfl_xor_sync(0xffffffffu, p, o);
        float nm = fmaxf(m, p);
        float f  = __expf(m - nm);
        float w  = __expf(p - nm);
        den = den * f + w;
        acc = acc * f + w * vc;
        m = nm;
    }
    float val = eluf(acc / den + bias[tid]);
    hout[i * FD + tid] = val;
    if (POOL) {
        int g = load_idx(batch, i, g_is64);
        atomicAdd(&g_pool[g * FD + tid], val);
        if (tid == 0) atomicAdd(&g_cnt[g], 1.0f);
    }
}

// ------------------- final head -------------------
__global__ void k_final(const float* __restrict__ lw, const float* __restrict__ lb,
                        float* __restrict__ out)
{
    __shared__ float sh[NCLS];
    int g = blockIdx.x;
    int j = threadIdx.x;
    if (j < NCLS) {
        float cnt = fmaxf(g_cnt[g], 1.0f);
        float s = lb[j];
        for (int f = 0; f < FD; f++)
            s += (g_pool[g * FD + f] / cnt) * lw[f * NCLS + j];
        sh[j] = eluf(s);
    }
    __syncthreads();
    if (j < NCLS) {
        float mx = NEG_BIG;
#pragma unroll
        for (int jj = 0; jj < NCLS; jj++) mx = fmaxf(mx, sh[jj]);
        float ls = 0.0f;
#pragma unroll
        for (int jj = 0; jj < NCLS; jj++) ls += __expf(sh[jj] - mx);
        out[g * NCLS + j] = sh[j] - mx - __logf(ls);
    }
}

// ------------------- launch -------------------
extern "C" void kernel_launch(void* const* d_in, const int* in_sizes, int n_in,
                              void* d_out, int out_size)
{
    const float* x    = (const float*)d_in[0];
    const void*  ei   = d_in[1];
    const void*  bat  = d_in[2];
    const float* Wl   = (const float*)d_in[3];
    const float* Wr   = (const float*)d_in[4];
    const float* bl   = (const float*)d_in[5];
    const float* br   = (const float*)d_in[6];
    const float* att  = (const float*)d_in[7];
    const float* bias = (const float*)d_in[8];
    const float* lw   = (const float*)d_in[9];
    const float* lb   = (const float*)d_in[10];
    float* out = (float*)d_out;

    const int gblocks = (NN + 127) / 128;   // 391

    // order: the ncu slot (-s 5 -c 1) lands on k_gemm_w<0,0,0>
    k_detect<<<1, 32>>>((const long long*)ei);                        // 0
    k_init<<<(NN + 255) / 256, 256>>>();                              // 1
    k_convW<<<(3 * FD * FD + 255) / 256, 256>>>(Wl, Wr);              // 2
    k_hist<<<(NE + 255) / 256, 256>>>(ei);                            // 3
    k_scan1<<<SCAN_NB, SCAN_B>>>();                                   // 4
    k_gemm_w<0, 0, 0><<<gblocks, 256>>>(x, bl + 0 * FD);              // 5  <- profiled
    k_gemm_w<0, 1, 1><<<gblocks, 256>>>(x, br + 0 * FD);
    k_scan2<<<1, 32>>>();
    k_scan3<<<SCAN_NB, SCAN_B>>>();
    k_scatter<<<(ET + 255) / 256, 256>>>(ei);
    k_aggr<0, 0><<<NN, FD>>>(att + 0 * FD, bias + 0 * FD, bat);

    k_gemm_w<1, 0, 2><<<gblocks, 256>>>(x, bl + 1 * FD);
    k_gemm_w<1, 1, 3><<<gblocks, 256>>>(x, br + 1 * FD);
    k_aggr<1, 0><<<NN, FD>>>(att + 1 * FD, bias + 1 * FD, bat);

    k_gemm_w<2, 0, 4><<<gblocks, 256>>>(x, bl + 2 * FD);
    k_gemm_w<2, 1, 5><<<gblocks, 256>>>(x, br + 2 * FD);
    k_aggr<0, 1><<<NN, FD>>>(att + 2 * FD, bias + 2 * FD, bat);

    k_final<<<NG, 32>>>(lw, lb, out);
}

// round 9
// speedup vs baseline: 1.2921x; 1.0328x over previous
#include <cuda_runtime.h>
#include <cuda_bf16.h>
#include <cstdint>

// Problem constants
#define NN 50000
#define NE 800000
#define ET 850000
#define NG 64
#define FD 128
#define NCLS 10
#define NEG_SLOPE 0.2f
#define SCAN_B 512
#define SCAN_NB ((NN + SCAN_B - 1) / SCAN_B)
#define NEG_BIG -3.0e38f

// ------------------- device scratch -------------------
__device__ float g_xl[NN * FD];
__device__ float g_xr[NN * FD];
__device__ float g_h0[NN * FD];
__device__ float g_h1[NN * FD];
__device__ __nv_bfloat16 g_wthi[6 * FD * FD];   // [layer*2+side][n][k]
__device__ __nv_bfloat16 g_wtlo[6 * FD * FD];
__device__ int   g_deg[NN];
__device__ int   g_excl[NN];
__device__ int   g_blk[SCAN_NB];
__device__ int   g_rowptr[NN + 1];
__device__ int   g_fill[NN];
__device__ int   g_src[ET];
__device__ float g_pool[NG * FD];
__device__ float g_cnt[NG];
__device__ int   g_is64;

__device__ __forceinline__ float eluf(float x) {
    return x > 0.0f ? x : (__expf(x) - 1.0f);
}

__device__ __forceinline__ int load_idx(const void* p, long long i, int is64) {
    if (is64) return (int)(((const long long*)p)[i]);
    return ((const int*)p)[i];
}

__device__ __forceinline__ uint32_t pack_bf2(float a, float b) {
    __nv_bfloat162 h = __floats2bfloat162_rn(a, b);
    return *(uint32_t*)&h;
}

__device__ __forceinline__ uint32_t smem_u32(const void* p) {
    uint32_t a;
    asm("{ .reg .u64 t; cvta.to.shared.u64 t, %1; cvt.u32.u64 %0, t; }" : "=r"(a) : "l"(p));
    return a;
}

// ------------------- dtype detection -------------------
__global__ void k_detect(const long long* __restrict__ ei) {
    if (threadIdx.x == 0 && blockIdx.x == 0) {
        int ok64 = 1;
        for (int i = 0; i < 64; i++) {
            long long v = ei[i];
            if (v < 0 || v >= (long long)NN) { ok64 = 0; break; }
        }
        g_is64 = ok64;
    }
}

// ------------------- CSR build -------------------
__global__ void k_init() {
    int i = blockIdx.x * blockDim.x + threadIdx.x;
    if (i < NN) { g_deg[i] = 1; g_fill[i] = 0; }
    if (i < NG * FD) g_pool[i] = 0.0f;
    if (i < NG) g_cnt[i] = 0.0f;
}

__global__ void k_hist(const void* __restrict__ ei) {
    int e = blockIdx.x * blockDim.x + threadIdx.x;
    if (e < NE) atomicAdd(&g_deg[load_idx(ei, (long long)NE + e, g_is64)], 1);
}

__global__ void k_scan1() {
    __shared__ int sm[SCAN_B];
    int i = blockIdx.x * SCAN_B + threadIdx.x;
    int v = (i < NN) ? g_deg[i] : 0;
    sm[threadIdx.x] = v;
    __syncthreads();
    for (int o = 1; o < SCAN_B; o <<= 1) {
        int t = (threadIdx.x >= o) ? sm[threadIdx.x - o] : 0;
        __syncthreads();
        sm[threadIdx.x] += t;
        __syncthreads();
    }
    if (i < NN) g_excl[i] = sm[threadIdx.x] - v;
    if (threadIdx.x == SCAN_B - 1) g_blk[blockIdx.x] = sm[SCAN_B - 1];
}

__global__ void k_scan2() {
    if (threadIdx.x == 0) {
        int run = 0;
        for (int b = 0; b < SCAN_NB; b++) { int t = g_blk[b]; g_blk[b] = run; run += t; }
        g_rowptr[NN] = ET;
    }
}

__global__ void k_scan3() {
    int i = blockIdx.x * SCAN_B + threadIdx.x;
    if (i < NN) g_rowptr[i] = g_excl[i] + g_blk[blockIdx.x];
}

__global__ void k_scatter(const void* __restrict__ ei) {
    int e = blockIdx.x * blockDim.x + threadIdx.x;
    if (e >= ET) return;
    int s, d;
    if (e < NE) {
        int is64 = g_is64;
        s = load_idx(ei, e, is64);
        d = load_idx(ei, (long long)NE + e, is64);
    } else {
        s = e - NE; d = e - NE;
    }
    int pos = g_rowptr[d] + atomicAdd(&g_fill[d], 1);
    g_src[pos] = s;
}

// ------------------- W transpose + hi/lo split (one-time) -------------------
__global__ void k_convW(const float* __restrict__ Wl, const float* __restrict__ Wr) {
    int i = blockIdx.x * blockDim.x + threadIdx.x;   // over 3*128*128
    if (i >= 3 * FD * FD) return;
    int l = i >> 14, r = i & 16383;
    int k = r >> 7, n = r & 127;
    float a = Wl[l * FD * FD + k * FD + n];
    __nv_bfloat16 ah = __float2bfloat16(a);
    g_wthi[(l * 2 + 0) * FD * FD + n * FD + k] = ah;
    g_wtlo[(l * 2 + 0) * FD * FD + n * FD + k] = __float2bfloat16(a - __bfloat162float(ah));
    float b = Wr[l * FD * FD + k * FD + n];
    __nv_bfloat16 bh = __float2bfloat16(b);
    g_wthi[(l * 2 + 1) * FD * FD + n * FD + k] = bh;
    g_wtlo[(l * 2 + 1) * FD * FD + n * FD + k] = __float2bfloat16(b - __bfloat162float(bh));
}

// ------------------- mma.sync bf16 split-2 GEMM with ldmatrix -------------------
// 128x128 block tile, 8 warps (warp = 32m x 64n), K chunked by 32.
// smem rows stride 40 bf16 (80 B): LDSM 8-row address sets hit 8 distinct bank-groups.
#define KSTR 40

#define MMA_BF16(c, a, b0v, b1v) \
    asm volatile("mma.sync.aligned.m16n8k16.row.col.f32.bf16.bf16.f32 " \
        "{%0,%1,%2,%3}, {%4,%5,%6,%7}, {%8,%9}, {%0,%1,%2,%3};" \
        : "+f"((c)[0]), "+f"((c)[1]), "+f"((c)[2]), "+f"((c)[3]) \
        : "r"((a)[0]), "r"((a)[1]), "r"((a)[2]), "r"((a)[3]), "r"(b0v), "r"(b1v))

#define LDSM_X4(r, addr) \
    asm volatile("ldmatrix.sync.aligned.m8n8.x4.shared.b16 {%0,%1,%2,%3}, [%4];" \
        : "=r"((r)[0]), "=r"((r)[1]), "=r"((r)[2]), "=r"((r)[3]) : "r"(addr))

template<int ASEL, int SIDE, int WIDX>
__global__ void __launch_bounds__(256, 2) k_gemm_w(const float* __restrict__ Aparam,
                                                   const float* __restrict__ bias)
{
    const float* A = (ASEL == 0) ? Aparam : (ASEL == 1 ? g_h0 : g_h1);
    float* out     = SIDE ? g_xr : g_xl;

    __shared__ __nv_bfloat16 sAhi[128 * KSTR];
    __shared__ __nv_bfloat16 sAlo[128 * KSTR];
    __shared__ __nv_bfloat16 sWhi[128 * KSTR];
    __shared__ __nv_bfloat16 sWlo[128 * KSTR];

    const int tid  = threadIdx.x;
    const int wid  = tid >> 5;
    const int lane = tid & 31;
    const int grp  = lane >> 2;        // 0..7 (epilogue row group)
    const int tig  = lane & 3;         // 0..3
    const int mstrip = (wid & 3) * 32;
    const int nstrip = (wid >> 2) * 64;
    const int rowBase = blockIdx.x * 128;

    // ldmatrix lane-address setup (constant across k-iterations)
    const int i8 = lane & 7;
    const int g  = lane >> 3;          // 0..3
    const uint32_t aHiB = smem_u32(sAhi), aLoB = smem_u32(sAlo);
    const uint32_t wHiB = smem_u32(sWhi), wLoB = smem_u32(sWlo);
    uint32_t aOff[2], bOff[4];
#pragma unroll
    for (int mt = 0; mt < 2; mt++) {
        int arow = mstrip + mt * 16 + i8 + ((g & 1) << 3);
        int akof = (g >> 1) << 3;
        aOff[mt] = (uint32_t)(arow * KSTR + akof) * 2u;
    }
#pragma unroll
    for (int p = 0; p < 4; p++) {
        int nrow = nstrip + p * 16 + i8 + ((g >> 1) << 3);
        int bkof = (g & 1) << 3;
        bOff[p] = (uint32_t)(nrow * KSTR + bkof) * 2u;
    }

    float acc[2][8][4];
#pragma unroll
    for (int mt = 0; mt < 2; mt++)
#pragma unroll
        for (int nt = 0; nt < 8; nt++)
#pragma unroll
            for (int q = 0; q < 4; q++) acc[mt][nt][q] = 0.0f;

    for (int kb = 0; kb < FD; kb += 32) {
        // ---- A: fp32 -> bf16 hi/lo into smem (4 float4 per thread) ----
#pragma unroll
        for (int i = 0; i < 4; i++) {
            int f = tid + i * 256;          // 0..1023
            int r = f >> 3;
            int c = (f & 7) * 4;
            int gr = rowBase + r;
            float4 v = make_float4(0.f, 0.f, 0.f, 0.f);
            if (gr < NN) v = *(const float4*)&A[(size_t)gr * FD + kb + c];
            __nv_bfloat16 hx = __float2bfloat16(v.x), hy = __float2bfloat16(v.y);
            __nv_bfloat16 hz = __float2bfloat16(v.z), hw = __float2bfloat16(v.w);
            uint32_t h0 = pack_bf2(__bfloat162float(hx), __bfloat162float(hy));
            uint32_t h1 = pack_bf2(__bfloat162float(hz), __bfloat162float(hw));
            uint32_t l0 = pack_bf2(v.x - __bfloat162float(hx), v.y - __bfloat162float(hy));
            uint32_t l1 = pack_bf2(v.z - __bfloat162float(hz), v.w - __bfloat162float(hw));
            int si = r * KSTR + c;
            *(uint32_t*)&sAhi[si]     = h0;
            *(uint32_t*)&sAhi[si + 2] = h1;
            *(uint32_t*)&sAlo[si]     = l0;
            *(uint32_t*)&sAlo[si + 2] = l1;
        }
        // ---- W tiles: bf16 [n][k] -> smem ----
        const __nv_bfloat16* wh = &g_wthi[(size_t)WIDX * FD * FD];
        const __nv_bfloat16* wl = &g_wtlo[(size_t)WIDX * FD * FD];
#pragma unroll
        for (int i = 0; i < 2; i++) {
            int f = tid + i * 256;          // 0..511
            int n = f >> 2;
            int c8 = (f & 3) * 8;
            uint4 vh = *(const uint4*)&wh[(size_t)n * FD + kb + c8];
            uint4 vl = *(const uint4*)&wl[(size_t)n * FD + kb + c8];
            int si = n * KSTR + c8;
            *(uint4*)&sWhi[si] = vh;
            *(uint4*)&sWlo[si] = vl;
        }
        __syncthreads();

#pragma unroll
        for (int s = 0; s < 2; s++) {
            const uint32_t soff = (uint32_t)s * 32u;   // 16 bf16 = 32 B
            uint32_t ah[2][4], al[2][4];
#pragma unroll
            for (int mt = 0; mt < 2; mt++) {
                LDSM_X4(ah[mt], aHiB + aOff[mt] + soff);
                LDSM_X4(al[mt], aLoB + aOff[mt] + soff);
            }
#pragma unroll
            for (int p = 0; p < 4; p++) {
                uint32_t bh[4], bl[4];
                LDSM_X4(bh, wHiB + bOff[p] + soff);
                LDSM_X4(bl, wLoB + bOff[p] + soff);
                const int nt0 = 2 * p, nt1 = 2 * p + 1;
#pragma unroll
                for (int mt = 0; mt < 2; mt++) {
                    MMA_BF16(acc[mt][nt0], ah[mt], bh[0], bh[1]);
                    MMA_BF16(acc[mt][nt0], al[mt], bh[0], bh[1]);
                    MMA_BF16(acc[mt][nt0], ah[mt], bl[0], bl[1]);
                    MMA_BF16(acc[mt][nt1], ah[mt], bh[2], bh[3]);
                    MMA_BF16(acc[mt][nt1], al[mt], bh[2], bh[3]);
                    MMA_BF16(acc[mt][nt1], ah[mt], bl[2], bl[3]);
                }
            }
        }
        __syncthreads();
    }

    // ---- epilogue ----
#pragma unroll
    for (int nt = 0; nt < 8; nt++) {
        int col = nstrip + nt * 8 + 2 * tig;
        float2 bv = *(const float2*)&bias[col];
#pragma unroll
        for (int mt = 0; mt < 2; mt++) {
            int r0 = rowBase + mstrip + mt * 16 + grp;
            if (r0 < NN) {
                float2 o0 = make_float2(acc[mt][nt][0] + bv.x, acc[mt][nt][1] + bv.y);
                *(float2*)&out[(size_t)r0 * FD + col] = o0;
            }
            if (r0 + 8 < NN) {
                float2 o1 = make_float2(acc[mt][nt][2] + bv.x, acc[mt][nt][3] + bv.y);
                *(float2*)&out[(size_t)(r0 + 8) * FD + col] = o1;
            }
        }
    }
}

// ------------------- fused edge scoring + online softmax + aggregation -------------------
template<int OSEL, int POOL>
__global__ void __launch_bounds__(128) k_aggr(const float* __restrict__ att,
                                              const float* __restrict__ bias,
                                              const void* __restrict__ batch)
{
    float* hout = (OSEL == 0) ? g_h0 : g_h1;
    int i   = blockIdx.x;
    int tid = threadIdx.x;

    float rx = g_xr[i * FD + tid];
    float at = att[tid];
    int beg = g_rowptr[i], end = g_rowptr[i + 1];

    float m = NEG_BIG, den = 0.0f, acc = 0.0f;

    int s = g_src[beg];
    float v = g_xl[s * FD + tid];
    for (int e = beg; e < end; e++) {
        float vc = v;
        int en = e + 1;
        if (en < end) {
            int sn = g_src[en];
            v = g_xl[sn * FD + tid];
        }
        float t  = vc + rx;
        float lr = t > 0.0f ? t : NEG_SLOPE * t;
        float p  = lr * at;
#pragma unroll
        for (int o = 16; o; o >>= 1) p += __shfl_xor_sync(0xffffffffu, p, o);
        float nm = fmaxf(m, p);
        float f  = __expf(m - nm);
        float w  = __expf(p - nm);
        den = den * f + w;
        acc = acc * f + w * vc;
        m = nm;
    }
    float val = eluf(acc / den + bias[tid]);
    hout[i * FD + tid] = val;
    if (POOL) {
        int g = load_idx(batch, i, g_is64);
        atomicAdd(&g_pool[g * FD + tid], val);
        if (tid == 0) atomicAdd(&g_cnt[g], 1.0f);
    }
}

// ------------------- final head -------------------
__global__ void k_final(const float* __restrict__ lw, const float* __restrict__ lb,
                        float* __restrict__ out)
{
    __shared__ float sh[NCLS];
    int g = blockIdx.x;
    int j = threadIdx.x;
    if (j < NCLS) {
        float cnt = fmaxf(g_cnt[g], 1.0f);
        float s = lb[j];
        for (int f = 0; f < FD; f++)
            s += (g_pool[g * FD + f] / cnt) * lw[f * NCLS + j];
        sh[j] = eluf(s);
    }
    __syncthreads();
    if (j < NCLS) {
        float mx = NEG_BIG;
#pragma unroll
        for (int jj = 0; jj < NCLS; jj++) mx = fmaxf(mx, sh[jj]);
        float ls = 0.0f;
#pragma unroll
        for (int jj = 0; jj < NCLS; jj++) ls += __expf(sh[jj] - mx);
        out[g * NCLS + j] = sh[j] - mx - __logf(ls);
    }
}

// ------------------- launch -------------------
extern "C" void kernel_launch(void* const* d_in, const int* in_sizes, int n_in,
                              void* d_out, int out_size)
{
    const float* x    = (const float*)d_in[0];
    const void*  ei   = d_in[1];
    const void*  bat  = d_in[2];
    const float* Wl   = (const float*)d_in[3];
    const float* Wr   = (const float*)d_in[4];
    const float* bl   = (const float*)d_in[5];
    const float* br   = (const float*)d_in[6];
    const float* att  = (const float*)d_in[7];
    const float* bias = (const float*)d_in[8];
    const float* lw   = (const float*)d_in[9];
    const float* lb   = (const float*)d_in[10];
    float* out = (float*)d_out;

    const int gblocks = (NN + 127) / 128;   // 391

    // stream-launch index 3 appears to be the profiled one -> park gemm<0,0,0> there
    k_detect<<<1, 32>>>((const long long*)ei);                        // 0
    k_init<<<(NN + 255) / 256, 256>>>();                              // 1
    k_convW<<<(3 * FD * FD + 255) / 256, 256>>>(Wl, Wr);              // 2
    k_gemm_w<0, 0, 0><<<gblocks, 256>>>(x, bl + 0 * FD);              // 3  <- profiled?
    k_gemm_w<0, 1, 1><<<gblocks, 256>>>(x, br + 0 * FD);              // 4
    k_hist<<<(NE + 255) / 256, 256>>>(ei);                            // 5
    k_scan1<<<SCAN_NB, SCAN_B>>>();
    k_scan2<<<1, 32>>>();
    k_scan3<<<SCAN_NB, SCAN_B>>>();
    k_scatter<<<(ET + 255) / 256, 256>>>(ei);
    k_aggr<0, 0><<<NN, FD>>>(att + 0 * FD, bias + 0 * FD, bat);

    k_gemm_w<1, 0, 2><<<gblocks, 256>>>(x, bl + 1 * FD);
    k_gemm_w<1, 1, 3><<<gblocks, 256>>>(x, br + 1 * FD);
    k_aggr<1, 0><<<NN, FD>>>(att + 1 * FD, bias + 1 * FD, bat);

    k_gemm_w<2, 0, 4><<<gblocks, 256>>>(x, bl + 2 * FD);
    k_gemm_w<2, 1, 5><<<gblocks, 256>>>(x, br + 2 * FD);
    k_aggr<0, 1><<<NN, FD>>>(att + 2 * FD, bias + 2 * FD, bat);

    k_final<<<NG, 32>>>(lw, lb, out);
}

// round 11
// speedup vs baseline: 1.3834x; 1.0707x over previous
#include <cuda_runtime.h>
#include <cuda_bf16.h>
#include <cstdint>

// Problem constants
#define NN 50000
#define NE 800000
#define ET 850000
#define NG 64
#define FD 128
#define NCLS 10
#define NEG_SLOPE 0.2f
#define SCAN_B 512
#define SCAN_NB ((NN + SCAN_B - 1) / SCAN_B)
#define NEG_BIG -3.0e38f

// ------------------- device scratch -------------------
__device__ float g_xl[NN * FD];
__device__ float g_xr[NN * FD];
__device__ float g_h0[NN * FD];
__device__ float g_h1[NN * FD];
__device__ __nv_bfloat16 g_wthi[6 * FD * FD];   // [layer*2+side][n][k]
__device__ __nv_bfloat16 g_wtlo[6 * FD * FD];
__device__ int   g_deg[NN];
__device__ int   g_excl[NN];
__device__ int   g_blk[SCAN_NB];
__device__ int   g_rowptr[NN + 1];
__device__ int   g_fill[NN];
__device__ int   g_src[ET];
__device__ float g_pool[NG * FD];
__device__ float g_cnt[NG];
__device__ int   g_is64;

__device__ __forceinline__ float eluf(float x) {
    return x > 0.0f ? x : (__expf(x) - 1.0f);
}

__device__ __forceinline__ int load_idx(const void* p, long long i, int is64) {
    if (is64) return (int)(((const long long*)p)[i]);
    return ((const int*)p)[i];
}

__device__ __forceinline__ uint32_t pack_bf2(float a, float b) {
    __nv_bfloat162 h = __floats2bfloat162_rn(a, b);
    return *(uint32_t*)&h;
}

__device__ __forceinline__ uint32_t smem_u32(const void* p) {
    uint32_t a;
    asm("{ .reg .u64 t; cvta.to.shared.u64 t, %1; cvt.u32.u64 %0, t; }" : "=r"(a) : "l"(p));
    return a;
}

// ------------------- dtype detection -------------------
__global__ void k_detect(const long long* __restrict__ ei) {
    if (threadIdx.x == 0 && blockIdx.x == 0) {
        int ok64 = 1;
        for (int i = 0; i < 64; i++) {
            long long v = ei[i];
            if (v < 0 || v >= (long long)NN) { ok64 = 0; break; }
        }
        g_is64 = ok64;
    }
}

// ------------------- CSR build -------------------
__global__ void k_init() {
    int i = blockIdx.x * blockDim.x + threadIdx.x;
    if (i < NN) { g_deg[i] = 1; g_fill[i] = 0; }
    if (i < NG * FD) g_pool[i] = 0.0f;
    if (i < NG) g_cnt[i] = 0.0f;
}

__global__ void k_hist(const void* __restrict__ ei) {
    int e = blockIdx.x * blockDim.x + threadIdx.x;
    if (e < NE) atomicAdd(&g_deg[load_idx(ei, (long long)NE + e, g_is64)], 1);
}

__global__ void k_scan1() {
    __shared__ int sm[SCAN_B];
    int i = blockIdx.x * SCAN_B + threadIdx.x;
    int v = (i < NN) ? g_deg[i] : 0;
    sm[threadIdx.x] = v;
    __syncthreads();
    for (int o = 1; o < SCAN_B; o <<= 1) {
        int t = (threadIdx.x >= o) ? sm[threadIdx.x - o] : 0;
        __syncthreads();
        sm[threadIdx.x] += t;
        __syncthreads();
    }
    if (i < NN) g_excl[i] = sm[threadIdx.x] - v;
    if (threadIdx.x == SCAN_B - 1) g_blk[blockIdx.x] = sm[SCAN_B - 1];
}

__global__ void k_scan2() {
    if (threadIdx.x == 0) {
        int run = 0;
        for (int b = 0; b < SCAN_NB; b++) { int t = g_blk[b]; g_blk[b] = run; run += t; }
        g_rowptr[NN] = ET;
    }
}

__global__ void k_scan3() {
    int i = blockIdx.x * SCAN_B + threadIdx.x;
    if (i < NN) g_rowptr[i] = g_excl[i] + g_blk[blockIdx.x];
}

__global__ void k_scatter(const void* __restrict__ ei) {
    int e = blockIdx.x * blockDim.x + threadIdx.x;
    if (e >= ET) return;
    int s, d;
    if (e < NE) {
        int is64 = g_is64;
        s = load_idx(ei, e, is64);
        d = load_idx(ei, (long long)NE + e, is64);
    } else {
        s = e - NE; d = e - NE;
    }
    int pos = g_rowptr[d] + atomicAdd(&g_fill[d], 1);
    g_src[pos] = s;
}

// ------------------- W transpose + hi/lo split (one-time) -------------------
__global__ void k_convW(const float* __restrict__ Wl, const float* __restrict__ Wr) {
    int i = blockIdx.x * blockDim.x + threadIdx.x;   // over 3*128*128
    if (i >= 3 * FD * FD) return;
    int l = i >> 14, r = i & 16383;
    int k = r >> 7, n = r & 127;
    float a = Wl[l * FD * FD + k * FD + n];
    __nv_bfloat16 ah = __float2bfloat16(a);
    g_wthi[(l * 2 + 0) * FD * FD + n * FD + k] = ah;
    g_wtlo[(l * 2 + 0) * FD * FD + n * FD + k] = __float2bfloat16(a - __bfloat162float(ah));
    float b = Wr[l * FD * FD + k * FD + n];
    __nv_bfloat16 bh = __float2bfloat16(b);
    g_wthi[(l * 2 + 1) * FD * FD + n * FD + k] = bh;
    g_wtlo[(l * 2 + 1) * FD * FD + n * FD + k] = __float2bfloat16(b - __bfloat162float(bh));
}

// ------------------- mma.sync bf16 split-2 GEMM with ldmatrix (proven R9) -------------------
// 128x128 block tile, 8 warps (warp = 32m x 64n), K chunked by 32.
// smem rows stride 40 bf16 (80 B): LDSM 8-row address sets hit 8 distinct bank-groups.
#define KSTR 40

#define MMA_BF16(c, a, b0v, b1v) \
    asm volatile("mma.sync.aligned.m16n8k16.row.col.f32.bf16.bf16.f32 " \
        "{%0,%1,%2,%3}, {%4,%5,%6,%7}, {%8,%9}, {%0,%1,%2,%3};" \
        : "+f"((c)[0]), "+f"((c)[1]), "+f"((c)[2]), "+f"((c)[3]) \
        : "r"((a)[0]), "r"((a)[1]), "r"((a)[2]), "r"((a)[3]), "r"(b0v), "r"(b1v))

#define LDSM_X4(r, addr) \
    asm volatile("ldmatrix.sync.aligned.m8n8.x4.shared.b16 {%0,%1,%2,%3}, [%4];" \
        : "=r"((r)[0]), "=r"((r)[1]), "=r"((r)[2]), "=r"((r)[3]) : "r"(addr))

template<int ASEL, int SIDE, int WIDX>
__global__ void __launch_bounds__(256, 2) k_gemm_w(const float* __restrict__ Aparam,
                                                   const float* __restrict__ bias)
{
    const float* A = (ASEL == 0) ? Aparam : (ASEL == 1 ? g_h0 : g_h1);
    float* out     = SIDE ? g_xr : g_xl;

    __shared__ __nv_bfloat16 sAhi[128 * KSTR];
    __shared__ __nv_bfloat16 sAlo[128 * KSTR];
    __shared__ __nv_bfloat16 sWhi[128 * KSTR];
    __shared__ __nv_bfloat16 sWlo[128 * KSTR];

    const int tid  = threadIdx.x;
    const int wid  = tid >> 5;
    const int lane = tid & 31;
    const int grp  = lane >> 2;        // 0..7 (epilogue row group)
    const int tig  = lane & 3;         // 0..3
    const int mstrip = (wid & 3) * 32;
    const int nstrip = (wid >> 2) * 64;
    const int rowBase = blockIdx.x * 128;

    // ldmatrix lane-address setup (constant across k-iterations)
    const int i8 = lane & 7;
    const int g  = lane >> 3;          // 0..3
    const uint32_t aHiB = smem_u32(sAhi), aLoB = smem_u32(sAlo);
    const uint32_t wHiB = smem_u32(sWhi), wLoB = smem_u32(sWlo);
    uint32_t aOff[2], bOff[4];
#pragma unroll
    for (int mt = 0; mt < 2; mt++) {
        int arow = mstrip + mt * 16 + i8 + ((g & 1) << 3);
        int akof = (g >> 1) << 3;
        aOff[mt] = (uint32_t)(arow * KSTR + akof) * 2u;
    }
#pragma unroll
    for (int p = 0; p < 4; p++) {
        int nrow = nstrip + p * 16 + i8 + ((g >> 1) << 3);
        int bkof = (g & 1) << 3;
        bOff[p] = (uint32_t)(nrow * KSTR + bkof) * 2u;
    }

    float acc[2][8][4];
#pragma unroll
    for (int mt = 0; mt < 2; mt++)
#pragma unroll
        for (int nt = 0; nt < 8; nt++)
#pragma unroll
            for (int q = 0; q < 4; q++) acc[mt][nt][q] = 0.0f;

    for (int kb = 0; kb < FD; kb += 32) {
        // ---- A: fp32 -> bf16 hi/lo into smem (4 float4 per thread) ----
#pragma unroll
        for (int i = 0; i < 4; i++) {
            int f = tid + i * 256;          // 0..1023
            int r = f >> 3;
            int c = (f & 7) * 4;
            int gr = rowBase + r;
            float4 v = make_float4(0.f, 0.f, 0.f, 0.f);
            if (gr < NN) v = *(const float4*)&A[(size_t)gr * FD + kb + c];
            __nv_bfloat16 hx = __float2bfloat16(v.x), hy = __float2bfloat16(v.y);
            __nv_bfloat16 hz = __float2bfloat16(v.z), hw = __float2bfloat16(v.w);
            uint32_t h0 = pack_bf2(__bfloat162float(hx), __bfloat162float(hy));
            uint32_t h1 = pack_bf2(__bfloat162float(hz), __bfloat162float(hw));
            uint32_t l0 = pack_bf2(v.x - __bfloat162float(hx), v.y - __bfloat162float(hy));
            uint32_t l1 = pack_bf2(v.z - __bfloat162float(hz), v.w - __bfloat162float(hw));
            int si = r * KSTR + c;
            *(uint32_t*)&sAhi[si]     = h0;
            *(uint32_t*)&sAhi[si + 2] = h1;
            *(uint32_t*)&sAlo[si]     = l0;
            *(uint32_t*)&sAlo[si + 2] = l1;
        }
        // ---- W tiles: bf16 [n][k] -> smem ----
        const __nv_bfloat16* wh = &g_wthi[(size_t)WIDX * FD * FD];
        const __nv_bfloat16* wl = &g_wtlo[(size_t)WIDX * FD * FD];
#pragma unroll
        for (int i = 0; i < 2; i++) {
            int f = tid + i * 256;          // 0..511
            int n = f >> 2;
            int c8 = (f & 3) * 8;
            uint4 vh = *(const uint4*)&wh[(size_t)n * FD + kb + c8];
            uint4 vl = *(const uint4*)&wl[(size_t)n * FD + kb + c8];
            int si = n * KSTR + c8;
            *(uint4*)&sWhi[si] = vh;
            *(uint4*)&sWlo[si] = vl;
        }
        __syncthreads();

#pragma unroll
        for (int s = 0; s < 2; s++) {
            const uint32_t soff = (uint32_t)s * 32u;   // 16 bf16 = 32 B
            uint32_t ah[2][4], al[2][4];
#pragma unroll
            for (int mt = 0; mt < 2; mt++) {
                LDSM_X4(ah[mt], aHiB + aOff[mt] + soff);
                LDSM_X4(al[mt], aLoB + aOff[mt] + soff);
            }
#pragma unroll
            for (int p = 0; p < 4; p++) {
                uint32_t bh[4], bl[4];
                LDSM_X4(bh, wHiB + bOff[p] + soff);
                LDSM_X4(bl, wLoB + bOff[p] + soff);
                const int nt0 = 2 * p, nt1 = 2 * p + 1;
#pragma unroll
                for (int mt = 0; mt < 2; mt++) {
                    MMA_BF16(acc[mt][nt0], ah[mt], bh[0], bh[1]);
                    MMA_BF16(acc[mt][nt0], al[mt], bh[0], bh[1]);
                    MMA_BF16(acc[mt][nt0], ah[mt], bl[0], bl[1]);
                    MMA_BF16(acc[mt][nt1], ah[mt], bh[2], bh[3]);
                    MMA_BF16(acc[mt][nt1], al[mt], bh[2], bh[3]);
                    MMA_BF16(acc[mt][nt1], ah[mt], bl[2], bl[3]);
                }
            }
        }
        __syncthreads();
    }

    // ---- epilogue ----
#pragma unroll
    for (int nt = 0; nt < 8; nt++) {
        int col = nstrip + nt * 8 + 2 * tig;
        float2 bv = *(const float2*)&bias[col];
#pragma unroll
        for (int mt = 0; mt < 2; mt++) {
            int r0 = rowBase + mstrip + mt * 16 + grp;
            if (r0 < NN) {
                float2 o0 = make_float2(acc[mt][nt][0] + bv.x, acc[mt][nt][1] + bv.y);
                *(float2*)&out[(size_t)r0 * FD + col] = o0;
            }
            if (r0 + 8 < NN) {
                float2 o1 = make_float2(acc[mt][nt][2] + bv.x, acc[mt][nt][3] + bv.y);
                *(float2*)&out[(size_t)(r0 + 8) * FD + col] = o1;
            }
        }
    }
}

// ------------------- fused edge scoring + online softmax + aggregation -------------------
// 2-edge interleaved butterflies to overlap the SHFL latency chains.
template<int OSEL, int POOL>
__global__ void __launch_bounds__(128) k_aggr(const float* __restrict__ att,
                                              const float* __restrict__ bias,
                                              const void* __restrict__ batch)
{
    float* hout = (OSEL == 0) ? g_h0 : g_h1;
    int i   = blockIdx.x;
    int tid = threadIdx.x;

    float rx = g_xr[i * FD + tid];
    float at = att[tid];
    int beg = g_rowptr[i], end = g_rowptr[i + 1];

    float m = NEG_BIG, den = 0.0f, acc = 0.0f;
    int e = beg;

    // odd-count head: one single edge
    if ((end - beg) & 1) {
        int s0 = g_src[e];
        float v0 = g_xl[s0 * FD + tid];
        float t0 = v0 + rx;
        float p0 = (t0 > 0.0f ? t0 : NEG_SLOPE * t0) * at;
#pragma unroll
        for (int o = 16; o; o >>= 1) p0 += __shfl_xor_sync(0xffffffffu, p0, o);
        float nm = fmaxf(m, p0);
        float f  = __expf(m - nm);
        float w  = __expf(p0 - nm);
        den = den * f + w;
        acc = acc * f + w * v0;
        m = nm;
        e++;
    }

    for (; e < end; e += 2) {
        int s0 = g_src[e], s1 = g_src[e + 1];
        float v0 = g_xl[s0 * FD + tid];
        float v1 = g_xl[s1 * FD + tid];
        float t0 = v0 + rx, t1 = v1 + rx;
        float p0 = (t0 > 0.0f ? t0 : NEG_SLOPE * t0) * at;
        float p1 = (t1 > 0.0f ? t1 : NEG_SLOPE * t1) * at;
#pragma unroll
        for (int o = 16; o; o >>= 1) {
            p0 += __shfl_xor_sync(0xffffffffu, p0, o);
            p1 += __shfl_xor_sync(0xffffffffu, p1, o);
        }
        float nm0 = fmaxf(m, p0);
        float f0  = __expf(m - nm0);
        float w0  = __expf(p0 - nm0);
        den = den * f0 + w0;
        acc = acc * f0 + w0 * v0;
        float nm1 = fmaxf(nm0, p1);
        float f1  = __expf(nm0 - nm1);
        float w1  = __expf(p1 - nm1);
        den = den * f1 + w1;
        acc = acc * f1 + w1 * v1;
        m = nm1;
    }

    float val = eluf(acc / den + bias[tid]);
    hout[i * FD + tid] = val;
    if (POOL) {
        int g = load_idx(batch, i, g_is64);
        atomicAdd(&g_pool[g * FD + tid], val);
        if (tid == 0) atomicAdd(&g_cnt[g], 1.0f);
    }
}

// ------------------- final head -------------------
__global__ void k_final(const float* __restrict__ lw, const float* __restrict__ lb,
                        float* __restrict__ out)
{
    __shared__ float sh[NCLS];
    int g = blockIdx.x;
    int j = threadIdx.x;
    if (j < NCLS) {
        float cnt = fmaxf(g_cnt[g], 1.0f);
        float s = lb[j];
        for (int f = 0; f < FD; f++)
            s += (g_pool[g * FD + f] / cnt) * lw[f * NCLS + j];
        sh[j] = eluf(s);
    }
    __syncthreads();
    if (j < NCLS) {
        float mx = NEG_BIG;
#pragma unroll
        for (int jj = 0; jj < NCLS; jj++) mx = fmaxf(mx, sh[jj]);
        float ls = 0.0f;
#pragma unroll
        for (int jj = 0; jj < NCLS; jj++) ls += __expf(sh[jj] - mx);
        out[g * NCLS + j] = sh[j] - mx - __logf(ls);
    }
}

// ------------------- launch -------------------
extern "C" void kernel_launch(void* const* d_in, const int* in_sizes, int n_in,
                              void* d_out, int out_size)
{
    const float* x    = (const float*)d_in[0];
    const void*  ei   = d_in[1];
    const void*  bat  = d_in[2];
    const float* Wl   = (const float*)d_in[3];
    const float* Wr   = (const float*)d_in[4];
    const float* bl   = (const float*)d_in[5];
    const float* br   = (const float*)d_in[6];
    const float* att  = (const float*)d_in[7];
    const float* bias = (const float*)d_in[8];
    const float* lw   = (const float*)d_in[9];
    const float* lb   = (const float*)d_in[10];
    float* out = (float*)d_out;

    const int gblocks = (NN + 127) / 128;   // 391

    k_detect<<<1, 32>>>((const long long*)ei);                        // 0
    k_init<<<(NN + 255) / 256, 256>>>();                              // 1
    k_convW<<<(3 * FD * FD + 255) / 256, 256>>>(Wl, Wr);              // 2
    k_gemm_w<0, 0, 0><<<gblocks, 256>>>(x, bl + 0 * FD);              // 3  <- profiled
    k_gemm_w<0, 1, 1><<<gblocks, 256>>>(x, br + 0 * FD);              // 4
    k_hist<<<(NE + 255) / 256, 256>>>(ei);                            // 5
    k_scan1<<<SCAN_NB, SCAN_B>>>();
    k_scan2<<<1, 32>>>();
    k_scan3<<<SCAN_NB, SCAN_B>>>();
    k_scatter<<<(ET + 255) / 256, 256>>>(ei);
    k_aggr<0, 0><<<NN, FD>>>(att + 0 * FD, bias + 0 * FD, bat);

    k_gemm_w<1, 0, 2><<<gblocks, 256>>>(x, bl + 1 * FD);
    k_gemm_w<1, 1, 3><<<gblocks, 256>>>(x, br + 1 * FD);
    k_aggr<1, 0><<<NN, FD>>>(att + 1 * FD, bias + 1 * FD, bat);

    k_gemm_w<2, 0, 4><<<gblocks, 256>>>(x, bl + 2 * FD);
    k_gemm_w<2, 1, 5><<<gblocks, 256>>>(x, br + 2 * FD);
    k_aggr<0, 1><<<NN, FD>>>(att + 2 * FD, bias + 2 * FD, bat);

    k_final<<<NG, 32>>>(lw, lb, out);
}